// round 1
// baseline (speedup 1.0000x reference)
#include <cuda_runtime.h>
#include <cuda_bf16.h>

#define S_LEN 4096
#define EMB   768
#define NHEAD 12
#define HD    64
#define WIN   256

// Scratch for projected Q/K/V, laid out (S, H, D) == (s, h*64+d), contiguous.
__device__ float g_q[S_LEN * EMB];
__device__ float g_k[S_LEN * EMB];
__device__ float g_v[S_LEN * EMB];

// ---------------------------------------------------------------------------
// GEMM: out[m][n] = (sum_k X[m][k] * Wt[k][n] + bias[n]) * scale
// M=4096, N=768, K=768. BM=128, BN=64, BK=16, 256 threads, 8x4 per thread.
// ---------------------------------------------------------------------------
__global__ __launch_bounds__(256) void gemm_bias_kernel(
    const float* __restrict__ X, const float* __restrict__ Wt,
    const float* __restrict__ bias, float* __restrict__ out, float scale)
{
    __shared__ float As[16 * 128];  // As[k][m], transposed
    __shared__ float Bs[16 * 64];   // Bs[k][n]

    const int bm = blockIdx.y * 128;
    const int bn = blockIdx.x * 64;
    const int t  = threadIdx.x;
    const int tr = t >> 4;    // 0..15 -> m sub-tile
    const int tc = t & 15;    // 0..15 -> n sub-tile

    float acc[8][4];
#pragma unroll
    for (int i = 0; i < 8; i++)
#pragma unroll
        for (int j = 0; j < 4; j++) acc[i][j] = 0.f;

    for (int k0 = 0; k0 < EMB; k0 += 16) {
        // Load A tile (128x16) transposed into As
#pragma unroll
        for (int u = 0; u < 2; u++) {
            int vv  = t + u * 256;
            int row = vv >> 2;
            int c   = (vv & 3) * 4;
            float4 f = *reinterpret_cast<const float4*>(&X[(bm + row) * EMB + k0 + c]);
            As[(c + 0) * 128 + row] = f.x;
            As[(c + 1) * 128 + row] = f.y;
            As[(c + 2) * 128 + row] = f.z;
            As[(c + 3) * 128 + row] = f.w;
        }
        // Load B tile (16x64)
        {
            int row = t >> 4;
            int c   = (t & 15) * 4;
            float4 f = *reinterpret_cast<const float4*>(&Wt[(k0 + row) * EMB + bn + c]);
            *reinterpret_cast<float4*>(&Bs[row * 64 + c]) = f;
        }
        __syncthreads();

#pragma unroll
        for (int kk = 0; kk < 16; kk++) {
            float4 a0 = *reinterpret_cast<const float4*>(&As[kk * 128 + tr * 8]);
            float4 a1 = *reinterpret_cast<const float4*>(&As[kk * 128 + tr * 8 + 4]);
            float4 b  = *reinterpret_cast<const float4*>(&Bs[kk * 64 + tc * 4]);
            float am[8] = {a0.x, a0.y, a0.z, a0.w, a1.x, a1.y, a1.z, a1.w};
            float bv_[4] = {b.x, b.y, b.z, b.w};
#pragma unroll
            for (int i = 0; i < 8; i++)
#pragma unroll
                for (int j = 0; j < 4; j++) acc[i][j] += am[i] * bv_[j];
        }
        __syncthreads();
    }

#pragma unroll
    for (int i = 0; i < 8; i++) {
        int m = bm + tr * 8 + i;
#pragma unroll
        for (int j = 0; j < 4; j++) {
            int n = bn + tc * 4 + j;
            out[m * EMB + n] = (acc[i][j] + bias[n]) * scale;
        }
    }
}

// ---------------------------------------------------------------------------
// Fused banded flash attention.
// Block: 64-query tile x one head; 9 key chunks of 64 covering [i0-256, i0+320).
// Online softmax with running (m, l) per query, branchless -inf handling.
// ---------------------------------------------------------------------------
__global__ __launch_bounds__(256) void attn_kernel(
    const float* __restrict__ amask, const unsigned char* __restrict__ imask,
    float* __restrict__ out)
{
    extern __shared__ float sm[];
    float* sQ  = sm;                 // 64*64
    float* sK  = sQ + 64 * 64;       // 64*65 (padded)
    float* sV  = sK + 64 * 65;       // 64*65
    float* sS  = sV + 64 * 65;       // 64*65 scores/probs
    float* sM  = sS + 64 * 65;       // 64
    float* sL  = sM + 64;            // 64
    float* sSc = sL + 64;            // 64
    float* sFM = sSc + 64;           // 64 per-key additive mask

    const int i0 = blockIdx.x * 64;
    const int h  = blockIdx.y;
    const int t  = threadIdx.x;
    const float NEG_INF = __int_as_float(0xff800000u);

    // Load Q tile (already scaled by 1/sqrt(D) in projection)
#pragma unroll
    for (int u = 0; u < 4; u++) {
        int id = t + u * 256;
        int r = id >> 4, c = (id & 15) * 4;
        float4 f = *reinterpret_cast<const float4*>(&g_q[(i0 + r) * EMB + h * HD + c]);
        *reinterpret_cast<float4*>(&sQ[r * 64 + c]) = f;
    }
    if (t < 64) { sM[t] = NEG_INF; sL[t] = 0.f; }

    float acc[2][8];
#pragma unroll
    for (int a = 0; a < 2; a++)
#pragma unroll
        for (int b = 0; b < 8; b++) acc[a][b] = 0.f;
    __syncthreads();

    for (int c9 = 0; c9 < 9; c9++) {
        int jc0 = i0 - WIN + c9 * 64;
        if (jc0 >= S_LEN || jc0 + 63 < 0) continue;

        // Load K, V chunk (zeros for out-of-sequence rows)
#pragma unroll
        for (int u = 0; u < 4; u++) {
            int id = t + u * 256;
            int jl = id >> 4, cc = (id & 15) * 4;
            int jg = jc0 + jl;
            float4 fk = {0.f, 0.f, 0.f, 0.f};
            float4 fv = {0.f, 0.f, 0.f, 0.f};
            if (jg >= 0 && jg < S_LEN) {
                fk = *reinterpret_cast<const float4*>(&g_k[jg * EMB + h * HD + cc]);
                fv = *reinterpret_cast<const float4*>(&g_v[jg * EMB + h * HD + cc]);
            }
            float* pk = &sK[jl * 65 + cc];
            pk[0] = fk.x; pk[1] = fk.y; pk[2] = fk.z; pk[3] = fk.w;
            float* pv = &sV[jl * 65 + cc];
            pv[0] = fv.x; pv[1] = fv.y; pv[2] = fv.z; pv[3] = fv.w;
        }
        if (t < 64) {
            int jg = jc0 + t;
            float fm;
            if (jg < 0 || jg >= S_LEN) fm = NEG_INF;
            else fm = (amask[jg] != 0.f) ? -100000000.0f : 0.f;
            sFM[t] = fm;
        }
        __syncthreads();

        // --- Scores: 4 queries x 4 keys per thread ---
        {
            const int r0 = (t >> 4) * 4;
            const int j0 = (t & 15) * 4;
            float a[4][4];
#pragma unroll
            for (int i = 0; i < 4; i++)
#pragma unroll
                for (int j = 0; j < 4; j++) a[i][j] = 0.f;

#pragma unroll 8
            for (int d = 0; d < 64; ++d) {
                float q0 = sQ[(r0 + 0) * 64 + d];
                float q1 = sQ[(r0 + 1) * 64 + d];
                float q2 = sQ[(r0 + 2) * 64 + d];
                float q3 = sQ[(r0 + 3) * 64 + d];
                float k0v = sK[(j0 + 0) * 65 + d];
                float k1v = sK[(j0 + 1) * 65 + d];
                float k2v = sK[(j0 + 2) * 65 + d];
                float k3v = sK[(j0 + 3) * 65 + d];
                a[0][0] += q0 * k0v; a[0][1] += q0 * k1v; a[0][2] += q0 * k2v; a[0][3] += q0 * k3v;
                a[1][0] += q1 * k0v; a[1][1] += q1 * k1v; a[1][2] += q1 * k2v; a[1][3] += q1 * k3v;
                a[2][0] += q2 * k0v; a[2][1] += q2 * k1v; a[2][2] += q2 * k2v; a[2][3] += q2 * k3v;
                a[3][0] += q3 * k0v; a[3][1] += q3 * k1v; a[3][2] += q3 * k2v; a[3][3] += q3 * k3v;
            }
#pragma unroll
            for (int i = 0; i < 4; i++) {
                int gi = i0 + r0 + i;
#pragma unroll
                for (int j = 0; j < 4; j++) {
                    int gj = jc0 + j0 + j;
                    float s = a[i][j] + sFM[j0 + j];
                    if (gj < gi - WIN || gj > gi + WIN) s = NEG_INF;
                    sS[(r0 + i) * 65 + j0 + j] = s;
                }
            }
        }
        __syncthreads();

        // --- Online softmax update: 4 lanes per query (branchless -inf safe) ---
        {
            int r    = t >> 2;
            int base = (t & 3) * 16;
            float mloc = NEG_INF;
#pragma unroll
            for (int j = 0; j < 16; j++) mloc = fmaxf(mloc, sS[r * 65 + base + j]);
            mloc = fmaxf(mloc, __shfl_xor_sync(0xffffffffu, mloc, 1));
            mloc = fmaxf(mloc, __shfl_xor_sync(0xffffffffu, mloc, 2));
            float mold = sM[r];
            float mnew = fmaxf(mold, mloc);
            // mref: if the whole history is masked, exp(-inf - 0) == 0 everywhere
            float mref = (mnew == NEG_INF) ? 0.f : mnew;
            float lsum = 0.f;
#pragma unroll
            for (int j = 0; j < 16; j++) {
                float p = __expf(sS[r * 65 + base + j] - mref);
                sS[r * 65 + base + j] = p;
                lsum += p;
            }
            lsum += __shfl_xor_sync(0xffffffffu, lsum, 1);
            lsum += __shfl_xor_sync(0xffffffffu, lsum, 2);
            float scl = __expf(mold - mref);  // mold=-inf -> 0 (acc is 0 then)
            if ((t & 3) == 0) {
                sM[r]  = mnew;
                sL[r]  = sL[r] * scl + lsum;
                sSc[r] = scl;
            }
        }
        __syncthreads();

        // --- AV accumulate: 2 queries x 8 dims per thread ---
        {
            int rq = (t >> 3) * 2;
            int d0 = (t & 7) * 8;
            float s0 = sSc[rq], s1 = sSc[rq + 1];
#pragma unroll
            for (int b = 0; b < 8; b++) { acc[0][b] *= s0; acc[1][b] *= s1; }
#pragma unroll 4
            for (int j = 0; j < 64; j++) {
                float p0 = sS[rq * 65 + j];
                float p1 = sS[(rq + 1) * 65 + j];
#pragma unroll
                for (int b = 0; b < 8; b++) {
                    float vv = sV[j * 65 + d0 + b];
                    acc[0][b] += p0 * vv;
                    acc[1][b] += p1 * vv;
                }
            }
        }
        __syncthreads();
    }

    // --- Epilogue ---
    {
        int rq = (t >> 3) * 2;
        int d0 = (t & 7) * 8;
#pragma unroll
        for (int qq = 0; qq < 2; qq++) {
            int gi = i0 + rq + qq;
            float inv = 1.f / sL[rq + qq];   // diagonal always valid => sL > 0
            if (imask[gi]) inv = 0.f;        // is_index_masked zeroes probs
#pragma unroll
            for (int b = 0; b < 8; b++)
                out[gi * EMB + h * HD + d0 + b] = acc[qq][b] * inv;
        }
    }
}

// ---------------------------------------------------------------------------
extern "C" void kernel_launch(void* const* d_in, const int* in_sizes, int n_in,
                              void* d_out, int out_size)
{
    const float*         hs    = (const float*)d_in[0];
    const float*         amask = (const float*)d_in[1];
    const unsigned char* imask = (const unsigned char*)d_in[2];
    const float*         Wq    = (const float*)d_in[3];
    const float*         bq    = (const float*)d_in[4];
    const float*         Wk    = (const float*)d_in[5];
    const float*         bk    = (const float*)d_in[6];
    const float*         Wv    = (const float*)d_in[7];
    const float*         bv    = (const float*)d_in[8];
    float*               out   = (float*)d_out;

    float *q, *k, *v;
    cudaGetSymbolAddress((void**)&q, g_q);
    cudaGetSymbolAddress((void**)&k, g_k);
    cudaGetSymbolAddress((void**)&v, g_v);

    dim3 gg(EMB / 64, S_LEN / 128);
    gemm_bias_kernel<<<gg, 256>>>(hs, Wq, bq, q, 0.125f);  // 1/sqrt(64)
    gemm_bias_kernel<<<gg, 256>>>(hs, Wk, bk, k, 1.0f);
    gemm_bias_kernel<<<gg, 256>>>(hs, Wv, bv, v, 1.0f);

    const int smem_bytes = (64 * 64 + 3 * 64 * 65 + 4 * 64) * (int)sizeof(float);
    cudaFuncSetAttribute(attn_kernel, cudaFuncAttributeMaxDynamicSharedMemorySize, smem_bytes);
    attn_kernel<<<dim3(S_LEN / 64, NHEAD), 256, smem_bytes>>>(amask, imask, out);
}

// round 3
// speedup vs baseline: 1.4349x; 1.4349x over previous
#include <cuda_runtime.h>
#include <cuda_bf16.h>

#define S_LEN 4096
#define EMB   768
#define NHEAD 12
#define HD    64
#define WIN   256

// Scratch for projected Q/K/V, laid out (S, H, D) == (s, h*64+d), contiguous.
__device__ float g_q[S_LEN * EMB];
__device__ float g_k[S_LEN * EMB];
__device__ float g_v[S_LEN * EMB];

__device__ __forceinline__ unsigned f2tf32(float x) {
    unsigned r;
    asm("cvt.rna.tf32.f32 %0, %1;" : "=r"(r) : "f"(x));
    return r;
}

// ---------------------------------------------------------------------------
// tf32 tensor-core GEMM: out[m][n] = (sum_k X[m][k] * Wt[k][n] + bias[n]) * scale
// M=4096, N=768, K=768. BM=128, BN=64, BK=32. 256 threads = 8 warps (4m x 2n),
// warp tile 32x32 via mma.sync.m16n8k8 (2 m-frags x 4 n-frags).
// ---------------------------------------------------------------------------
__global__ __launch_bounds__(256) void gemm_tf32_kernel(
    const float* __restrict__ X, const float* __restrict__ Wt,
    const float* __restrict__ bias, float* __restrict__ out, float scale)
{
    __shared__ float As[128][36];  // [m][k], pad 4 -> frag loads bank = 4g+tg (unique)
    __shared__ float Bs[32][72];   // [k][n], pad 8 -> frag loads bank = 8tg+g (unique)

    const int bm   = blockIdx.y * 128;
    const int bn   = blockIdx.x * 64;
    const int t    = threadIdx.x;
    const int lane = t & 31;
    const int wid  = t >> 5;
    const int wm   = (wid & 3) * 32;   // warp m-offset
    const int wn   = (wid >> 2) * 32;  // warp n-offset
    const int g    = lane >> 2;        // 0..7
    const int tg   = lane & 3;         // 0..3

    float c[2][4][4];
#pragma unroll
    for (int mi = 0; mi < 2; mi++)
#pragma unroll
        for (int ni = 0; ni < 4; ni++)
#pragma unroll
            for (int j = 0; j < 4; j++) c[mi][ni][j] = 0.f;

    for (int k0 = 0; k0 < EMB; k0 += 32) {
        // Load A tile 128x32 (each thread: 4 float4 along k), cvt.rna -> tf32 bits
#pragma unroll
        for (int u = 0; u < 4; u++) {
            int vv  = t + u * 256;        // 0..1023
            int row = vv >> 3;            // 0..127
            int cc  = (vv & 7) * 4;       // 0..28
            float4 f = *reinterpret_cast<const float4*>(&X[(bm + row) * EMB + k0 + cc]);
            float4 o;
            o.x = __uint_as_float(f2tf32(f.x));
            o.y = __uint_as_float(f2tf32(f.y));
            o.z = __uint_as_float(f2tf32(f.z));
            o.w = __uint_as_float(f2tf32(f.w));
            *reinterpret_cast<float4*>(&As[row][cc]) = o;
        }
        // Load B tile 32x64
#pragma unroll
        for (int u = 0; u < 2; u++) {
            int vv  = t + u * 256;        // 0..511
            int row = vv >> 4;            // 0..31
            int cc  = (vv & 15) * 4;      // 0..60
            float4 f = *reinterpret_cast<const float4*>(&Wt[(k0 + row) * EMB + bn + cc]);
            float4 o;
            o.x = __uint_as_float(f2tf32(f.x));
            o.y = __uint_as_float(f2tf32(f.y));
            o.z = __uint_as_float(f2tf32(f.z));
            o.w = __uint_as_float(f2tf32(f.w));
            *reinterpret_cast<float4*>(&Bs[row][cc]) = o;
        }
        __syncthreads();

#pragma unroll
        for (int kk = 0; kk < 32; kk += 8) {
            unsigned a[2][4], b[4][2];
#pragma unroll
            for (int mi = 0; mi < 2; mi++) {
                int m0 = wm + mi * 16;
                a[mi][0] = __float_as_uint(As[m0 + g    ][kk + tg    ]);
                a[mi][1] = __float_as_uint(As[m0 + g + 8][kk + tg    ]);
                a[mi][2] = __float_as_uint(As[m0 + g    ][kk + tg + 4]);
                a[mi][3] = __float_as_uint(As[m0 + g + 8][kk + tg + 4]);
            }
#pragma unroll
            for (int ni = 0; ni < 4; ni++) {
                int n0 = wn + ni * 8;
                b[ni][0] = __float_as_uint(Bs[kk + tg    ][n0 + g]);
                b[ni][1] = __float_as_uint(Bs[kk + tg + 4][n0 + g]);
            }
#pragma unroll
            for (int mi = 0; mi < 2; mi++)
#pragma unroll
                for (int ni = 0; ni < 4; ni++) {
                    asm volatile(
                        "mma.sync.aligned.m16n8k8.row.col.f32.tf32.tf32.f32 "
                        "{%0,%1,%2,%3}, {%4,%5,%6,%7}, {%8,%9}, {%0,%1,%2,%3};"
                        : "+f"(c[mi][ni][0]), "+f"(c[mi][ni][1]),
                          "+f"(c[mi][ni][2]), "+f"(c[mi][ni][3])
                        : "r"(a[mi][0]), "r"(a[mi][1]), "r"(a[mi][2]), "r"(a[mi][3]),
                          "r"(b[ni][0]), "r"(b[ni][1]));
                }
        }
        __syncthreads();
    }

    // Epilogue: c0,c1 -> (row g, cols 2tg,2tg+1); c2,c3 -> row g+8
#pragma unroll
    for (int mi = 0; mi < 2; mi++)
#pragma unroll
        for (int ni = 0; ni < 4; ni++) {
            int row = bm + wm + mi * 16 + g;
            int col = bn + wn + ni * 8 + 2 * tg;
            float b0 = bias[col], b1 = bias[col + 1];
            out[row * EMB + col]           = (c[mi][ni][0] + b0) * scale;
            out[row * EMB + col + 1]       = (c[mi][ni][1] + b1) * scale;
            out[(row + 8) * EMB + col]     = (c[mi][ni][2] + b0) * scale;
            out[(row + 8) * EMB + col + 1] = (c[mi][ni][3] + b1) * scale;
        }
}

// ---------------------------------------------------------------------------
// Fused banded flash attention (unchanged from R1).
// ---------------------------------------------------------------------------
__global__ __launch_bounds__(256) void attn_kernel(
    const float* __restrict__ amask, const unsigned char* __restrict__ imask,
    float* __restrict__ out)
{
    extern __shared__ float sm[];
    float* sQ  = sm;                 // 64*64
    float* sK  = sQ + 64 * 64;       // 64*65 (padded)
    float* sV  = sK + 64 * 65;       // 64*65
    float* sS  = sV + 64 * 65;       // 64*65 scores/probs
    float* sM  = sS + 64 * 65;       // 64
    float* sL  = sM + 64;            // 64
    float* sSc = sL + 64;            // 64
    float* sFM = sSc + 64;           // 64 per-key additive mask

    const int i0 = blockIdx.x * 64;
    const int h  = blockIdx.y;
    const int t  = threadIdx.x;
    const float NEG_INF = __int_as_float(0xff800000u);

#pragma unroll
    for (int u = 0; u < 4; u++) {
        int id = t + u * 256;
        int r = id >> 4, c = (id & 15) * 4;
        float4 f = *reinterpret_cast<const float4*>(&g_q[(i0 + r) * EMB + h * HD + c]);
        *reinterpret_cast<float4*>(&sQ[r * 64 + c]) = f;
    }
    if (t < 64) { sM[t] = NEG_INF; sL[t] = 0.f; }

    float acc[2][8];
#pragma unroll
    for (int a = 0; a < 2; a++)
#pragma unroll
        for (int b = 0; b < 8; b++) acc[a][b] = 0.f;
    __syncthreads();

    for (int c9 = 0; c9 < 9; c9++) {
        int jc0 = i0 - WIN + c9 * 64;
        if (jc0 >= S_LEN || jc0 + 63 < 0) continue;

#pragma unroll
        for (int u = 0; u < 4; u++) {
            int id = t + u * 256;
            int jl = id >> 4, cc = (id & 15) * 4;
            int jg = jc0 + jl;
            float4 fk = {0.f, 0.f, 0.f, 0.f};
            float4 fv = {0.f, 0.f, 0.f, 0.f};
            if (jg >= 0 && jg < S_LEN) {
                fk = *reinterpret_cast<const float4*>(&g_k[jg * EMB + h * HD + cc]);
                fv = *reinterpret_cast<const float4*>(&g_v[jg * EMB + h * HD + cc]);
            }
            float* pk = &sK[jl * 65 + cc];
            pk[0] = fk.x; pk[1] = fk.y; pk[2] = fk.z; pk[3] = fk.w;
            float* pv = &sV[jl * 65 + cc];
            pv[0] = fv.x; pv[1] = fv.y; pv[2] = fv.z; pv[3] = fv.w;
        }
        if (t < 64) {
            int jg = jc0 + t;
            float fm;
            if (jg < 0 || jg >= S_LEN) fm = NEG_INF;
            else fm = (amask[jg] != 0.f) ? -100000000.0f : 0.f;
            sFM[t] = fm;
        }
        __syncthreads();

        {
            const int r0 = (t >> 4) * 4;
            const int j0 = (t & 15) * 4;
            float a[4][4];
#pragma unroll
            for (int i = 0; i < 4; i++)
#pragma unroll
                for (int j = 0; j < 4; j++) a[i][j] = 0.f;

#pragma unroll 8
            for (int d = 0; d < 64; ++d) {
                float q0 = sQ[(r0 + 0) * 64 + d];
                float q1 = sQ[(r0 + 1) * 64 + d];
                float q2 = sQ[(r0 + 2) * 64 + d];
                float q3 = sQ[(r0 + 3) * 64 + d];
                float k0v = sK[(j0 + 0) * 65 + d];
                float k1v = sK[(j0 + 1) * 65 + d];
                float k2v = sK[(j0 + 2) * 65 + d];
                float k3v = sK[(j0 + 3) * 65 + d];
                a[0][0] += q0 * k0v; a[0][1] += q0 * k1v; a[0][2] += q0 * k2v; a[0][3] += q0 * k3v;
                a[1][0] += q1 * k0v; a[1][1] += q1 * k1v; a[1][2] += q1 * k2v; a[1][3] += q1 * k3v;
                a[2][0] += q2 * k0v; a[2][1] += q2 * k1v; a[2][2] += q2 * k2v; a[2][3] += q2 * k3v;
                a[3][0] += q3 * k0v; a[3][1] += q3 * k1v; a[3][2] += q3 * k2v; a[3][3] += q3 * k3v;
            }
#pragma unroll
            for (int i = 0; i < 4; i++) {
                int gi = i0 + r0 + i;
#pragma unroll
                for (int j = 0; j < 4; j++) {
                    int gj = jc0 + j0 + j;
                    float s = a[i][j] + sFM[j0 + j];
                    if (gj < gi - WIN || gj > gi + WIN) s = NEG_INF;
                    sS[(r0 + i) * 65 + j0 + j] = s;
                }
            }
        }
        __syncthreads();

        {
            int r    = t >> 2;
            int base = (t & 3) * 16;
            float mloc = NEG_INF;
#pragma unroll
            for (int j = 0; j < 16; j++) mloc = fmaxf(mloc, sS[r * 65 + base + j]);
            mloc = fmaxf(mloc, __shfl_xor_sync(0xffffffffu, mloc, 1));
            mloc = fmaxf(mloc, __shfl_xor_sync(0xffffffffu, mloc, 2));
            float mold = sM[r];
            float mnew = fmaxf(mold, mloc);
            float mref = (mnew == NEG_INF) ? 0.f : mnew;
            float lsum = 0.f;
#pragma unroll
            for (int j = 0; j < 16; j++) {
                float p = __expf(sS[r * 65 + base + j] - mref);
                sS[r * 65 + base + j] = p;
                lsum += p;
            }
            lsum += __shfl_xor_sync(0xffffffffu, lsum, 1);
            lsum += __shfl_xor_sync(0xffffffffu, lsum, 2);
            float scl = __expf(mold - mref);
            if ((t & 3) == 0) {
                sM[r]  = mnew;
                sL[r]  = sL[r] * scl + lsum;
                sSc[r] = scl;
            }
        }
        __syncthreads();

        {
            int rq = (t >> 3) * 2;
            int d0 = (t & 7) * 8;
            float s0 = sSc[rq], s1 = sSc[rq + 1];
#pragma unroll
            for (int b = 0; b < 8; b++) { acc[0][b] *= s0; acc[1][b] *= s1; }
#pragma unroll 4
            for (int j = 0; j < 64; j++) {
                float p0 = sS[rq * 65 + j];
                float p1 = sS[(rq + 1) * 65 + j];
#pragma unroll
                for (int b = 0; b < 8; b++) {
                    float vv = sV[j * 65 + d0 + b];
                    acc[0][b] += p0 * vv;
                    acc[1][b] += p1 * vv;
                }
            }
        }
        __syncthreads();
    }

    {
        int rq = (t >> 3) * 2;
        int d0 = (t & 7) * 8;
#pragma unroll
        for (int qq = 0; qq < 2; qq++) {
            int gi = i0 + rq + qq;
            float inv = 1.f / sL[rq + qq];
            if (imask[gi]) inv = 0.f;
#pragma unroll
            for (int b = 0; b < 8; b++)
                out[gi * EMB + h * HD + d0 + b] = acc[qq][b] * inv;
        }
    }
}

// ---------------------------------------------------------------------------
extern "C" void kernel_launch(void* const* d_in, const int* in_sizes, int n_in,
                              void* d_out, int out_size)
{
    const float*         hs    = (const float*)d_in[0];
    const float*         amask = (const float*)d_in[1];
    const unsigned char* imask = (const unsigned char*)d_in[2];
    const float*         Wq    = (const float*)d_in[3];
    const float*         bq    = (const float*)d_in[4];
    const float*         Wk    = (const float*)d_in[5];
    const float*         bk    = (const float*)d_in[6];
    const float*         Wv    = (const float*)d_in[7];
    const float*         bv    = (const float*)d_in[8];
    float*               out   = (float*)d_out;

    float *q, *k, *v;
    cudaGetSymbolAddress((void**)&q, g_q);
    cudaGetSymbolAddress((void**)&k, g_k);
    cudaGetSymbolAddress((void**)&v, g_v);

    dim3 gg(EMB / 64, S_LEN / 128);
    gemm_tf32_kernel<<<gg, 256>>>(hs, Wq, bq, q, 0.125f);  // 1/sqrt(64)
    gemm_tf32_kernel<<<gg, 256>>>(hs, Wk, bk, k, 1.0f);
    gemm_tf32_kernel<<<gg, 256>>>(hs, Wv, bv, v, 1.0f);

    const int smem_bytes = (64 * 64 + 3 * 64 * 65 + 4 * 64) * (int)sizeof(float);
    cudaFuncSetAttribute(attn_kernel, cudaFuncAttributeMaxDynamicSharedMemorySize, smem_bytes);
    attn_kernel<<<dim3(S_LEN / 64, NHEAD), 256, smem_bytes>>>(amask, imask, out);
}

// round 4
// speedup vs baseline: 2.9694x; 2.0695x over previous
#include <cuda_runtime.h>
#include <cuda_bf16.h>
#include <math_constants.h>

#define S_LEN 4096
#define EMB   768
#define NHEAD 12
#define HD    64
#define WIN   256

// Scratch for projected Q/K/V, laid out (S, H, D) == (s, h*64+d), contiguous.
__device__ float g_q[S_LEN * EMB];
__device__ float g_k[S_LEN * EMB];
__device__ float g_v[S_LEN * EMB];

__device__ __forceinline__ unsigned f2tf32(float x) {
    unsigned r;
    asm("cvt.rna.tf32.f32 %0, %1;" : "=r"(r) : "f"(x));
    return r;
}

__device__ __forceinline__ void mma_tf32(float c[4], const unsigned a[4],
                                         unsigned b0, unsigned b1) {
    asm volatile(
        "mma.sync.aligned.m16n8k8.row.col.f32.tf32.tf32.f32 "
        "{%0,%1,%2,%3}, {%4,%5,%6,%7}, {%8,%9}, {%0,%1,%2,%3};"
        : "+f"(c[0]), "+f"(c[1]), "+f"(c[2]), "+f"(c[3])
        : "r"(a[0]), "r"(a[1]), "r"(a[2]), "r"(a[3]), "r"(b0), "r"(b1));
}

// ---------------------------------------------------------------------------
// tf32 tensor-core GEMM (unchanged from R2).
// ---------------------------------------------------------------------------
__global__ __launch_bounds__(256) void gemm_tf32_kernel(
    const float* __restrict__ X, const float* __restrict__ Wt,
    const float* __restrict__ bias, float* __restrict__ out, float scale)
{
    __shared__ float As[128][36];
    __shared__ float Bs[32][72];

    const int bm   = blockIdx.y * 128;
    const int bn   = blockIdx.x * 64;
    const int t    = threadIdx.x;
    const int lane = t & 31;
    const int wid  = t >> 5;
    const int wm   = (wid & 3) * 32;
    const int wn   = (wid >> 2) * 32;
    const int g    = lane >> 2;
    const int tg   = lane & 3;

    float c[2][4][4];
#pragma unroll
    for (int mi = 0; mi < 2; mi++)
#pragma unroll
        for (int ni = 0; ni < 4; ni++)
#pragma unroll
            for (int j = 0; j < 4; j++) c[mi][ni][j] = 0.f;

    for (int k0 = 0; k0 < EMB; k0 += 32) {
#pragma unroll
        for (int u = 0; u < 4; u++) {
            int vv  = t + u * 256;
            int row = vv >> 3;
            int cc  = (vv & 7) * 4;
            float4 f = *reinterpret_cast<const float4*>(&X[(bm + row) * EMB + k0 + cc]);
            float4 o;
            o.x = __uint_as_float(f2tf32(f.x));
            o.y = __uint_as_float(f2tf32(f.y));
            o.z = __uint_as_float(f2tf32(f.z));
            o.w = __uint_as_float(f2tf32(f.w));
            *reinterpret_cast<float4*>(&As[row][cc]) = o;
        }
#pragma unroll
        for (int u = 0; u < 2; u++) {
            int vv  = t + u * 256;
            int row = vv >> 4;
            int cc  = (vv & 15) * 4;
            float4 f = *reinterpret_cast<const float4*>(&Wt[(k0 + row) * EMB + bn + cc]);
            float4 o;
            o.x = __uint_as_float(f2tf32(f.x));
            o.y = __uint_as_float(f2tf32(f.y));
            o.z = __uint_as_float(f2tf32(f.z));
            o.w = __uint_as_float(f2tf32(f.w));
            *reinterpret_cast<float4*>(&Bs[row][cc]) = o;
        }
        __syncthreads();

#pragma unroll
        for (int kk = 0; kk < 32; kk += 8) {
            unsigned a[2][4], b[4][2];
#pragma unroll
            for (int mi = 0; mi < 2; mi++) {
                int m0 = wm + mi * 16;
                a[mi][0] = __float_as_uint(As[m0 + g    ][kk + tg    ]);
                a[mi][1] = __float_as_uint(As[m0 + g + 8][kk + tg    ]);
                a[mi][2] = __float_as_uint(As[m0 + g    ][kk + tg + 4]);
                a[mi][3] = __float_as_uint(As[m0 + g + 8][kk + tg + 4]);
            }
#pragma unroll
            for (int ni = 0; ni < 4; ni++) {
                int n0 = wn + ni * 8;
                b[ni][0] = __float_as_uint(Bs[kk + tg    ][n0 + g]);
                b[ni][1] = __float_as_uint(Bs[kk + tg + 4][n0 + g]);
            }
#pragma unroll
            for (int mi = 0; mi < 2; mi++)
#pragma unroll
                for (int ni = 0; ni < 4; ni++)
                    mma_tf32(c[mi][ni], a[mi], b[ni][0], b[ni][1]);
        }
        __syncthreads();
    }

#pragma unroll
    for (int mi = 0; mi < 2; mi++)
#pragma unroll
        for (int ni = 0; ni < 4; ni++) {
            int row = bm + wm + mi * 16 + g;
            int col = bn + wn + ni * 8 + 2 * tg;
            float b0 = bias[col], b1 = bias[col + 1];
            out[row * EMB + col]           = (c[mi][ni][0] + b0) * scale;
            out[row * EMB + col + 1]       = (c[mi][ni][1] + b1) * scale;
            out[(row + 8) * EMB + col]     = (c[mi][ni][2] + b0) * scale;
            out[(row + 8) * EMB + col + 1] = (c[mi][ni][3] + b1) * scale;
        }
}

// ---------------------------------------------------------------------------
// Tensor-core banded flash attention.
// Block = 64 queries x 1 head, 128 threads = 4 warps; each warp owns 16 queries.
// Q fragments in registers for the whole kernel; K/V (tf32) staged in smem.
// Softmax in registers on the mma C-fragment layout; P->A-frag via shuffles.
// ---------------------------------------------------------------------------
__global__ __launch_bounds__(128) void attn_mma_kernel(
    const float* __restrict__ amask, const unsigned char* __restrict__ imask,
    float* __restrict__ out)
{
    __shared__ float sK[64 * 68];   // stride 68: K-frag bank = 4g+tg (unique)
    __shared__ float sV[64 * 72];   // stride 72: V-frag bank = 8tg+g (unique)
    __shared__ float sFM[64];

    const int i0   = blockIdx.x * 64;
    const int h    = blockIdx.y;
    const int t    = threadIdx.x;
    const int lane = t & 31;
    const int warp = t >> 5;
    const int g    = lane >> 2;
    const int tg   = lane & 3;
    const int qrow = i0 + warp * 16;
    const float NEG_INF = -CUDART_INF_F;

    // Load Q fragments once (rows qrow+g, qrow+g+8; cols kk*8+tg, +tg+4)
    unsigned aq[8][4];
    {
        const float* qp = g_q + (size_t)qrow * EMB + h * HD;
#pragma unroll
        for (int kk = 0; kk < 8; kk++) {
            aq[kk][0] = f2tf32(qp[g * EMB + kk * 8 + tg]);
            aq[kk][1] = f2tf32(qp[(g + 8) * EMB + kk * 8 + tg]);
            aq[kk][2] = f2tf32(qp[g * EMB + kk * 8 + tg + 4]);
            aq[kk][3] = f2tf32(qp[(g + 8) * EMB + kk * 8 + tg + 4]);
        }
    }

    float o[8][4];
#pragma unroll
    for (int ni = 0; ni < 8; ni++)
#pragma unroll
        for (int j = 0; j < 4; j++) o[ni][j] = 0.f;

    float mA = NEG_INF, mB = NEG_INF, lA = 0.f, lB = 0.f;
    const int giA = qrow + g;
    const int giB = giA + 8;

    for (int c9 = 0; c9 < 9; c9++) {
        const int jc0 = i0 - WIN + c9 * 64;
        if (jc0 + 63 < 0 || jc0 >= S_LEN) continue;

        __syncthreads();  // previous chunk's smem reads done before refill
        // Stage K, V (tf32-converted) and the additive key mask
#pragma unroll
        for (int u = 0; u < 8; u++) {
            int vv = t + u * 128;          // 0..1023
            int r  = vv >> 4;              // 0..63
            int c4 = (vv & 15) * 4;        // 0..60
            int jg = jc0 + r;
            float4 fk = {0.f, 0.f, 0.f, 0.f};
            float4 fv = {0.f, 0.f, 0.f, 0.f};
            if (jg >= 0 && jg < S_LEN) {
                fk = *reinterpret_cast<const float4*>(&g_k[(size_t)jg * EMB + h * HD + c4]);
                fv = *reinterpret_cast<const float4*>(&g_v[(size_t)jg * EMB + h * HD + c4]);
            }
            float4 ok, ov;
            ok.x = __uint_as_float(f2tf32(fk.x));
            ok.y = __uint_as_float(f2tf32(fk.y));
            ok.z = __uint_as_float(f2tf32(fk.z));
            ok.w = __uint_as_float(f2tf32(fk.w));
            ov.x = __uint_as_float(f2tf32(fv.x));
            ov.y = __uint_as_float(f2tf32(fv.y));
            ov.z = __uint_as_float(f2tf32(fv.z));
            ov.w = __uint_as_float(f2tf32(fv.w));
            *reinterpret_cast<float4*>(&sK[r * 68 + c4]) = ok;
            *reinterpret_cast<float4*>(&sV[r * 72 + c4]) = ov;
        }
        if (t < 64) {
            int jg = jc0 + t;
            float fm;
            if (jg < 0 || jg >= S_LEN) fm = NEG_INF;
            else fm = (amask[jg] != 0.f) ? -100000000.0f : 0.f;
            sFM[t] = fm;
        }
        __syncthreads();

        // --- S = Q K^T on tensor cores ---
        float s[8][4];
#pragma unroll
        for (int ni = 0; ni < 8; ni++)
#pragma unroll
            for (int j = 0; j < 4; j++) s[ni][j] = 0.f;

#pragma unroll
        for (int kk = 0; kk < 8; kk++) {
#pragma unroll
            for (int ni = 0; ni < 8; ni++) {
                unsigned b0 = __float_as_uint(sK[(ni * 8 + g) * 68 + kk * 8 + tg]);
                unsigned b1 = __float_as_uint(sK[(ni * 8 + g) * 68 + kk * 8 + tg + 4]);
                mma_tf32(s[ni], aq[kk], b0, b1);
            }
        }

        // --- mask + register softmax ---
        float mxA = NEG_INF, mxB = NEG_INF;
#pragma unroll
        for (int ni = 0; ni < 8; ni++) {
            int jl0 = ni * 8 + 2 * tg;
#pragma unroll
            for (int jj = 0; jj < 2; jj++) {
                int   gj = jc0 + jl0 + jj;
                float fm = sFM[jl0 + jj];
                float v0 = s[ni][jj] + fm;
                if (gj < giA - WIN || gj > giA + WIN) v0 = NEG_INF;
                s[ni][jj] = v0;
                mxA = fmaxf(mxA, v0);
                float v1 = s[ni][2 + jj] + fm;
                if (gj < giB - WIN || gj > giB + WIN) v1 = NEG_INF;
                s[ni][2 + jj] = v1;
                mxB = fmaxf(mxB, v1);
            }
        }
        mxA = fmaxf(mxA, __shfl_xor_sync(0xffffffffu, mxA, 1));
        mxA = fmaxf(mxA, __shfl_xor_sync(0xffffffffu, mxA, 2));
        mxB = fmaxf(mxB, __shfl_xor_sync(0xffffffffu, mxB, 1));
        mxB = fmaxf(mxB, __shfl_xor_sync(0xffffffffu, mxB, 2));

        float mnA = fmaxf(mA, mxA);
        float mnB = fmaxf(mB, mxB);
        float mrA = (mnA == NEG_INF) ? 0.f : mnA;
        float mrB = (mnB == NEG_INF) ? 0.f : mnB;

        float lsA = 0.f, lsB = 0.f;
#pragma unroll
        for (int ni = 0; ni < 8; ni++) {
#pragma unroll
            for (int jj = 0; jj < 2; jj++) {
                float p0 = __expf(s[ni][jj] - mrA);
                float p1 = __expf(s[ni][2 + jj] - mrB);
                s[ni][jj]     = p0;
                s[ni][2 + jj] = p1;
                lsA += p0;
                lsB += p1;
            }
        }
        lsA += __shfl_xor_sync(0xffffffffu, lsA, 1);
        lsA += __shfl_xor_sync(0xffffffffu, lsA, 2);
        lsB += __shfl_xor_sync(0xffffffffu, lsB, 1);
        lsB += __shfl_xor_sync(0xffffffffu, lsB, 2);

        float scA = __expf(mA - mrA);   // mA=-inf -> 0
        float scB = __expf(mB - mrB);
        lA = lA * scA + lsA;
        lB = lB * scB + lsB;
        mA = mnA;
        mB = mnB;
#pragma unroll
        for (int ni = 0; ni < 8; ni++) {
            o[ni][0] *= scA; o[ni][1] *= scA;
            o[ni][2] *= scB; o[ni][3] *= scB;
        }

        // Convert probs to tf32 in place (l-sums used full precision above)
#pragma unroll
        for (int ni = 0; ni < 8; ni++)
#pragma unroll
            for (int j = 0; j < 4; j++)
                s[ni][j] = __uint_as_float(f2tf32(s[ni][j]));

        // --- O += P V on tensor cores; C-frag -> A-frag via quad shuffles ---
        const int  src0 = (lane & 28) | (tg >> 1);
        const bool odd  = (tg & 1);
#pragma unroll
        for (int kk = 0; kk < 8; kk++) {
            float v00 = __shfl_sync(0xffffffffu, s[kk][0], src0);
            float v01 = __shfl_sync(0xffffffffu, s[kk][1], src0);
            float v02 = __shfl_sync(0xffffffffu, s[kk][2], src0);
            float v03 = __shfl_sync(0xffffffffu, s[kk][3], src0);
            float w00 = __shfl_sync(0xffffffffu, s[kk][0], src0 + 2);
            float w01 = __shfl_sync(0xffffffffu, s[kk][1], src0 + 2);
            float w02 = __shfl_sync(0xffffffffu, s[kk][2], src0 + 2);
            float w03 = __shfl_sync(0xffffffffu, s[kk][3], src0 + 2);
            unsigned ap[4];
            ap[0] = __float_as_uint(odd ? v01 : v00);  // P[g   ][kk*8+tg  ]
            ap[1] = __float_as_uint(odd ? v03 : v02);  // P[g+8 ][kk*8+tg  ]
            ap[2] = __float_as_uint(odd ? w01 : w00);  // P[g   ][kk*8+tg+4]
            ap[3] = __float_as_uint(odd ? w03 : w02);  // P[g+8 ][kk*8+tg+4]
#pragma unroll
            for (int ni = 0; ni < 8; ni++) {
                unsigned b0 = __float_as_uint(sV[(kk * 8 + tg) * 72 + ni * 8 + g]);
                unsigned b1 = __float_as_uint(sV[(kk * 8 + tg + 4) * 72 + ni * 8 + g]);
                mma_tf32(o[ni], ap, b0, b1);
            }
        }
    }

    // --- Epilogue: normalize, apply is_index_masked, coalesced v2 stores ---
    float invA = 1.f / lA;
    float invB = 1.f / lB;
    if (imask[giA]) invA = 0.f;
    if (imask[giB]) invB = 0.f;
    float* opA = out + (size_t)giA * EMB + h * HD;
    float* opB = out + (size_t)giB * EMB + h * HD;
#pragma unroll
    for (int ni = 0; ni < 8; ni++) {
        int col = ni * 8 + 2 * tg;
        float2 r0 = make_float2(o[ni][0] * invA, o[ni][1] * invA);
        float2 r1 = make_float2(o[ni][2] * invB, o[ni][3] * invB);
        *reinterpret_cast<float2*>(&opA[col]) = r0;
        *reinterpret_cast<float2*>(&opB[col]) = r1;
    }
}

// ---------------------------------------------------------------------------
extern "C" void kernel_launch(void* const* d_in, const int* in_sizes, int n_in,
                              void* d_out, int out_size)
{
    const float*         hs    = (const float*)d_in[0];
    const float*         amask = (const float*)d_in[1];
    const unsigned char* imask = (const unsigned char*)d_in[2];
    const float*         Wq    = (const float*)d_in[3];
    const float*         bq    = (const float*)d_in[4];
    const float*         Wk    = (const float*)d_in[5];
    const float*         bk    = (const float*)d_in[6];
    const float*         Wv    = (const float*)d_in[7];
    const float*         bv    = (const float*)d_in[8];
    float*               out   = (float*)d_out;

    float *q, *k, *v;
    cudaGetSymbolAddress((void**)&q, g_q);
    cudaGetSymbolAddress((void**)&k, g_k);
    cudaGetSymbolAddress((void**)&v, g_v);

    dim3 gg(EMB / 64, S_LEN / 128);
    gemm_tf32_kernel<<<gg, 256>>>(hs, Wq, bq, q, 0.125f);  // 1/sqrt(64)
    gemm_tf32_kernel<<<gg, 256>>>(hs, Wk, bk, k, 1.0f);
    gemm_tf32_kernel<<<gg, 256>>>(hs, Wv, bv, v, 1.0f);

    attn_mma_kernel<<<dim3(S_LEN / 64, NHEAD), 128>>>(amask, imask, out);
}